// round 5
// baseline (speedup 1.0000x reference)
#include <cuda_runtime.h>
#include <cuda_bf16.h>
#include <math.h>

#define Bq 4
#define Tq 1024
#define Hq 512
#define Pq 20
#define Vq 32000
#define NBLK_LSTM 128

// ---------------- scratch (static device allocations; no cudaMalloc) ----------------
__device__ float g_xW1[Bq * Tq * 4 * Hq];     // 33.5 MB
__device__ float g_xW2[Bq * Tq * 4 * Pq];     // 1.3 MB
__device__ float g_enc[Bq * Tq * Hq];         // 8.4 MB
__device__ float g_cat[Bq * Tq * 2 * Hq];     // 16.8 MB  [ctx | enc]
__device__ float g_comb[Bq * Tq * Hq];        // 8.4 MB
__device__ float g_attw[(size_t)Bq * Tq * Tq];// 16.8 MB
__device__ float g_mu[Bq * Tq];
__device__ float g_sigma[Bq * Tq];
__device__ unsigned g_bar_cnt = 0;
__device__ unsigned g_bar_gen = 0;

__device__ __forceinline__ float sigmoidf_(float x) { return 1.0f / (1.0f + expf(-x)); }

// =====================================================================
// Generic NT GEMM: C[M,N] = act(A[M,K] * B[N,K]^T + bias[N])
// A,B row-major (lda = ldb = K). Optional row gather on A (embedding).
// Block tile 128x128, BK=16, 256 threads, 8x8 microtile.
// M must be a multiple of 128; N is guarded.
// =====================================================================
template <int ACT>
__global__ void __launch_bounds__(256, 2) gemm_nt_kernel(
    const float* __restrict__ A, const float* __restrict__ Bm,
    const float* __restrict__ bias, float* __restrict__ C,
    int N, int K, int ldc, const int* __restrict__ a_rows)
{
    __shared__ float As[16][128];
    __shared__ float Bs[16][128];
    const int bm = blockIdx.y << 7;
    const int bn = blockIdx.x << 7;
    const int tid = threadIdx.x;
    const int lr = tid >> 2;          // 0..63
    const int lc = (tid & 3) << 2;    // 0,4,8,12

    const int am0 = bm + lr, am1 = bm + lr + 64;
    const float* Ar0 = A + (size_t)(a_rows ? a_rows[am0] : am0) * K + lc;
    const float* Ar1 = A + (size_t)(a_rows ? a_rows[am1] : am1) * K + lc;
    const int bn0 = bn + lr, bn1 = bn + lr + 64;
    const float* Br0 = (bn0 < N) ? (Bm + (size_t)bn0 * K + lc) : 0;
    const float* Br1 = (bn1 < N) ? (Bm + (size_t)bn1 * K + lc) : 0;

    const int ty = tid >> 4, tx = tid & 15;
    float acc[8][8];
#pragma unroll
    for (int i = 0; i < 8; i++)
#pragma unroll
        for (int j = 0; j < 8; j++) acc[i][j] = 0.f;

    for (int k0 = 0; k0 < K; k0 += 16) {
        float4 a0 = *(const float4*)(Ar0 + k0);
        float4 a1 = *(const float4*)(Ar1 + k0);
        float4 b0 = Br0 ? *(const float4*)(Br0 + k0) : make_float4(0.f, 0.f, 0.f, 0.f);
        float4 b1 = Br1 ? *(const float4*)(Br1 + k0) : make_float4(0.f, 0.f, 0.f, 0.f);
        __syncthreads();
        As[lc + 0][lr] = a0.x; As[lc + 1][lr] = a0.y; As[lc + 2][lr] = a0.z; As[lc + 3][lr] = a0.w;
        As[lc + 0][lr + 64] = a1.x; As[lc + 1][lr + 64] = a1.y; As[lc + 2][lr + 64] = a1.z; As[lc + 3][lr + 64] = a1.w;
        Bs[lc + 0][lr] = b0.x; Bs[lc + 1][lr] = b0.y; Bs[lc + 2][lr] = b0.z; Bs[lc + 3][lr] = b0.w;
        Bs[lc + 0][lr + 64] = b1.x; Bs[lc + 1][lr + 64] = b1.y; Bs[lc + 2][lr + 64] = b1.z; Bs[lc + 3][lr + 64] = b1.w;
        __syncthreads();
#pragma unroll
        for (int kk = 0; kk < 16; ++kk) {
            float av[8], bv[8];
            *(float4*)(av)     = *(const float4*)&As[kk][ty << 3];
            *(float4*)(av + 4) = *(const float4*)&As[kk][(ty << 3) + 4];
            *(float4*)(bv)     = *(const float4*)&Bs[kk][tx << 3];
            *(float4*)(bv + 4) = *(const float4*)&Bs[kk][(tx << 3) + 4];
#pragma unroll
            for (int i = 0; i < 8; i++)
#pragma unroll
                for (int j = 0; j < 8; j++) acc[i][j] = fmaf(av[i], bv[j], acc[i][j]);
        }
    }
#pragma unroll
    for (int i = 0; i < 8; i++) {
        const int row = bm + (ty << 3) + i;
        float* Cr = C + (size_t)row * ldc;
#pragma unroll
        for (int j = 0; j < 8; j++) {
            const int col = bn + (tx << 3) + j;
            if (col < N) {
                float v = acc[i][j] + (bias ? bias[col] : 0.f);
                if (ACT == 1) v = tanhf(v);
                Cr[col] = v;
            }
        }
    }
}

// =====================================================================
// Batched NN GEMM: C[M,N] = A[M,K] * B[K,N]; batch via blockIdx.z.
// M,N multiples of 128; K multiple of 16. ldb = N.
// =====================================================================
__global__ void __launch_bounds__(256, 2) gemm_nn_kernel(
    const float* __restrict__ A, const float* __restrict__ Bm,
    float* __restrict__ C, int N, int K, int ldb, int ldc,
    size_t sA, size_t sB, size_t sC)
{
    A += (size_t)blockIdx.z * sA;
    Bm += (size_t)blockIdx.z * sB;
    C += (size_t)blockIdx.z * sC;
    __shared__ float As[16][128];
    __shared__ float Bs[16][128];
    const int bm = blockIdx.y << 7, bn = blockIdx.x << 7;
    const int tid = threadIdx.x;
    const int lr = tid >> 2, lc = (tid & 3) << 2;
    const float* Ar0 = A + (size_t)(bm + lr) * K + lc;
    const float* Ar1 = A + (size_t)(bm + lr + 64) * K + lc;
    const int kb = tid >> 5;           // 0..7
    const int nb = (tid & 31) << 2;    // 0..124
    const float* Bp0 = Bm + (size_t)kb * ldb + bn + nb;
    const float* Bp1 = Bm + (size_t)(kb + 8) * ldb + bn + nb;

    const int ty = tid >> 4, tx = tid & 15;
    float acc[8][8];
#pragma unroll
    for (int i = 0; i < 8; i++)
#pragma unroll
        for (int j = 0; j < 8; j++) acc[i][j] = 0.f;

    for (int k0 = 0; k0 < K; k0 += 16) {
        float4 a0 = *(const float4*)(Ar0 + k0);
        float4 a1 = *(const float4*)(Ar1 + k0);
        float4 b0 = *(const float4*)(Bp0 + (size_t)k0 * ldb);
        float4 b1 = *(const float4*)(Bp1 + (size_t)k0 * ldb);
        __syncthreads();
        As[lc + 0][lr] = a0.x; As[lc + 1][lr] = a0.y; As[lc + 2][lr] = a0.z; As[lc + 3][lr] = a0.w;
        As[lc + 0][lr + 64] = a1.x; As[lc + 1][lr + 64] = a1.y; As[lc + 2][lr + 64] = a1.z; As[lc + 3][lr + 64] = a1.w;
        *(float4*)&Bs[kb][nb] = b0;
        *(float4*)&Bs[kb + 8][nb] = b1;
        __syncthreads();
#pragma unroll
        for (int kk = 0; kk < 16; ++kk) {
            float av[8], bv[8];
            *(float4*)(av)     = *(const float4*)&As[kk][ty << 3];
            *(float4*)(av + 4) = *(const float4*)&As[kk][(ty << 3) + 4];
            *(float4*)(bv)     = *(const float4*)&Bs[kk][tx << 3];
            *(float4*)(bv + 4) = *(const float4*)&Bs[kk][(tx << 3) + 4];
#pragma unroll
            for (int i = 0; i < 8; i++)
#pragma unroll
                for (int j = 0; j < 8; j++) acc[i][j] = fmaf(av[i], bv[j], acc[i][j]);
        }
    }
#pragma unroll
    for (int i = 0; i < 8; i++) {
        const int row = bm + (ty << 3) + i;
        float* Cr = C + (size_t)row * ldc + bn + (tx << 3);
#pragma unroll
        for (int j = 0; j < 8; j++) Cr[j] = acc[i][j];
    }
}

// =====================================================================
// Encoder LSTM: persistent kernel, 128 blocks x 256 threads.
// Block g owns hidden units j0..j0+3 (j0 = 4g): its 16 rows of Whh
// (i/f/g/o per unit) live in SMEM. Per step: GEMV partials + warp
// reductions, gate update by threads 0..15, then software grid barrier.
// Writes enc and the second half of cat.
// =====================================================================
__global__ void __launch_bounds__(256) lstm_enc_kernel(
    const float* __restrict__ Whh, const float* __restrict__ bhh)
{
    const int g = blockIdx.x;
    const int tid = threadIdx.x;
    __shared__ float Wsh[16][512];   // local row r = q*4+jj -> global row q*512 + j0 + jj
    __shared__ float hsh[4][512];
    __shared__ float gsum[16][4];
    const int j0 = g << 2;

    for (int i = tid; i < 16 * 512; i += 256) {
        const int r = i >> 9, c = i & 511;
        Wsh[r][c] = Whh[(size_t)((r >> 2) * 512 + j0 + (r & 3)) * 512 + c];
    }
    const int bb = tid >> 2, jj = tid & 3;   // for tid<16: gate-update role
    float bh[4] = {0.f, 0.f, 0.f, 0.f};
    if (tid < 16) {
#pragma unroll
        for (int q = 0; q < 4; q++) bh[q] = bhh[q * 512 + j0 + jj];
    }
    float cst = 0.f;
    unsigned gen = *(volatile unsigned*)&g_bar_gen;
    const int w = tid >> 5, lane = tid & 31;
    const int r0 = w << 1, r1 = r0 + 1;
    __syncthreads();

    for (int t = 0; t < Tq; ++t) {
        if (t == 0) {
            for (int i = tid; i < 2048; i += 256) ((float*)hsh)[i] = 0.f;
        } else {
            for (int i = tid; i < 2048; i += 256) {
                const int b = i >> 9, c = i & 511;
                ((float*)hsh)[i] = __ldcg(&g_enc[((size_t)b * Tq + (t - 1)) * Hq + c]);
            }
        }
        __syncthreads();

        float a0[4] = {0.f, 0.f, 0.f, 0.f}, a1[4] = {0.f, 0.f, 0.f, 0.f};
#pragma unroll 4
        for (int c = lane; c < 512; c += 32) {
            const float w0 = Wsh[r0][c], w1 = Wsh[r1][c];
#pragma unroll
            for (int b = 0; b < 4; b++) {
                const float hv = hsh[b][c];
                a0[b] = fmaf(w0, hv, a0[b]);
                a1[b] = fmaf(w1, hv, a1[b]);
            }
        }
#pragma unroll
        for (int off = 16; off; off >>= 1) {
#pragma unroll
            for (int b = 0; b < 4; b++) {
                a0[b] += __shfl_xor_sync(0xffffffffu, a0[b], off);
                a1[b] += __shfl_xor_sync(0xffffffffu, a1[b], off);
            }
        }
        if (lane == 0) {
#pragma unroll
            for (int b = 0; b < 4; b++) { gsum[r0][b] = a0[b]; gsum[r1][b] = a1[b]; }
        }
        __syncthreads();

        if (tid < 16) {
            float pre[4];
#pragma unroll
            for (int q = 0; q < 4; q++)
                pre[q] = __ldcg(&g_xW1[((size_t)bb * Tq + t) * 2048 + q * 512 + j0 + jj])
                         + gsum[(q << 2) + jj][bb] + bh[q];
            const float ig = sigmoidf_(pre[0]);
            const float fg = sigmoidf_(pre[1]);
            const float gg = tanhf(pre[2]);
            const float og = sigmoidf_(pre[3]);
            cst = fg * cst + ig * gg;
            const float h = og * tanhf(cst);
            g_enc[((size_t)bb * Tq + t) * Hq + j0 + jj] = h;
            g_cat[((size_t)bb * Tq + t) * 1024 + 512 + j0 + jj] = h;
            __threadfence();
        }
        __syncthreads();
        // --- grid barrier (sense via generation counter) ---
        if (tid == 0) {
            const unsigned target = gen + 1;
            const unsigned arrived = atomicAdd(&g_bar_cnt, 1u);
            if (arrived == NBLK_LSTM - 1) {
                g_bar_cnt = 0u;
                __threadfence();
                *(volatile unsigned*)&g_bar_gen = target;
            } else {
                while (*(volatile unsigned*)&g_bar_gen != target) {}
            }
            __threadfence();
        }
        gen++;
        __syncthreads();
    }
}

// =====================================================================
// Positional LSTM (P=20) + fused mw/sigma heads + mu scan.
// Single block, 320 threads: tid=(b*80+r) computes one gate preact;
// tid<80 does gate update; tid<4 does the mu/sigma heads + scan.
// =====================================================================
__global__ void __launch_bounds__(320) lstm_pw_kernel(
    const float* __restrict__ Wp_hh, const float* __restrict__ bp_hh,
    const float* __restrict__ Wmu, const float* __restrict__ bmu,
    const float* __restrict__ Wsig, const float* __restrict__ bsig,
    const int* __restrict__ pad_lengths)
{
    const int tid = threadIdx.x;
    __shared__ float hp[4][20];
    __shared__ float gs[4][80];
    const int b = tid / 80, r = tid - b * 80;
    float wrow[20];
#pragma unroll
    for (int c = 0; c < 20; c++) wrow[c] = Wp_hh[r * 20 + c];
    const float bsum = bp_hh[r];

    const int b2 = tid / 20, p = tid - b2 * 20;  // valid for tid<80
    float cst = 0.f;

    float invL = 0.f, muprev = 0.f;
    float wmu0[20], wmu1[20], wmu2[20], wsg[20];
    float bm0 = 0.f, bm1 = 0.f, bm2 = 0.f, bs0 = 0.f;
    if (tid < 4) {
        invL = 1.0f / (float)pad_lengths[tid];
#pragma unroll
        for (int c = 0; c < 20; c++) {
            wmu0[c] = Wmu[c]; wmu1[c] = Wmu[20 + c]; wmu2[c] = Wmu[40 + c];
            wsg[c] = Wsig[c];
        }
        bm0 = bmu[0]; bm1 = bmu[1]; bm2 = bmu[2]; bs0 = bsig[0];
    }
    if (tid < 80) hp[b2][p] = 0.f;
    __syncthreads();

    float xv = __ldcg(&g_xW2[(size_t)b * Tq * 80 + r]);  // t = 0 prefetch
    for (int t = 0; t < Tq; ++t) {
        float s = xv + bsum;
#pragma unroll
        for (int c = 0; c < 20; c++) s = fmaf(wrow[c], hp[b][c], s);
        gs[b][r] = s;
        if (t + 1 < Tq) xv = __ldcg(&g_xW2[((size_t)b * Tq + t + 1) * 80 + r]);
        __syncthreads();
        if (tid < 80) {
            const float ig = sigmoidf_(gs[b2][p]);
            const float fg = sigmoidf_(gs[b2][20 + p]);
            const float gg = tanhf(gs[b2][40 + p]);
            const float og = sigmoidf_(gs[b2][60 + p]);
            cst = fg * cst + ig * gg;
            hp[b2][p] = og * tanhf(cst);
        }
        __syncthreads();
        if (tid < 4) {
            float d0 = bm0, d1 = bm1, d2 = bm2, ds = bs0;
#pragma unroll
            for (int c = 0; c < 20; c++) {
                const float hv = hp[tid][c];
                d0 = fmaf(wmu0[c], hv, d0);
                d1 = fmaf(wmu1[c], hv, d1);
                d2 = fmaf(wmu2[c], hv, d2);
                ds = fmaf(wsg[c], hv, ds);
            }
            const float m0 = fmaxf(d0, 0.f), m1 = fmaxf(d1, 0.f), m2 = fmaxf(d2, 0.f);
            const float sg = sigmoidf_(ds);
            const float base = m1 * invL + m2 * ((float)(t + 1) * invL);
            muprev = m0 * muprev + base;
            g_mu[tid * Tq + t] = muprev;
            g_sigma[tid * Tq + t] = sg;
        }
        __syncthreads();
    }
}

// =====================================================================
// Attention weights: one block per (b, j). Gaussian over t/(j+1),
// causal mask t<=j, L1 normalize. Writes full row (zeros for t>j).
// =====================================================================
__global__ void __launch_bounds__(256) attn_w_kernel()
{
    const int j = blockIdx.x;
    const int b = blockIdx.y;
    const int tid = threadIdx.x;
    __shared__ float row[Tq];
    __shared__ float warpsum[8];
    __shared__ float invtot;
    const float m = g_mu[b * Tq + j];
    const float s = g_sigma[b * Tq + j];
    const float inv2s = 1.0f / (2.0f * s * s + 0.001f);
    const float jp1 = (float)(j + 1);
    float lsum = 0.f;
    for (int t = tid; t < Tq; t += 256) {
        float v = 0.f;
        if (t <= j) {
            const float d = (float)t / jp1 - m;
            v = expf(-(d * d) * inv2s);
        }
        row[t] = v;
        lsum += v;
    }
#pragma unroll
    for (int off = 16; off; off >>= 1) lsum += __shfl_xor_sync(0xffffffffu, lsum, off);
    if ((tid & 31) == 0) warpsum[tid >> 5] = lsum;
    __syncthreads();
    if (tid == 0) {
        float tot = 0.f;
#pragma unroll
        for (int i = 0; i < 8; i++) tot += warpsum[i];
        invtot = 1.0f / fmaxf(tot, 1e-12f);
    }
    __syncthreads();
    const float inv = invtot;
    float* out = &g_attw[((size_t)b * Tq + j) * Tq];
    for (int t = tid; t < Tq; t += 256) out[t] = row[t] * inv;
}

// =====================================================================
extern "C" void kernel_launch(void* const* d_in, const int* in_sizes, int n_in,
                              void* d_out, int out_size)
{
    (void)in_sizes; (void)n_in; (void)out_size;
    const int*   ids  = (const int*)d_in[0];
    const int*   padl = (const int*)d_in[1];
    const float* emb  = (const float*)d_in[2];
    const float* decb = (const float*)d_in[3];
    const float* Wih  = (const float*)d_in[4];
    const float* Whh  = (const float*)d_in[5];
    const float* bih  = (const float*)d_in[6];
    const float* bhh  = (const float*)d_in[7];
    const float* Wpih = (const float*)d_in[8];
    const float* Wphh = (const float*)d_in[9];
    const float* bpih = (const float*)d_in[10];
    const float* bphh = (const float*)d_in[11];
    const float* Wmu  = (const float*)d_in[12];
    const float* bmu  = (const float*)d_in[13];
    const float* Wsig = (const float*)d_in[14];
    const float* bsig = (const float*)d_in[15];
    const float* Wc   = (const float*)d_in[16];
    const float* bc   = (const float*)d_in[17];
    float* out = (float*)d_out;

    float *xW1, *xW2, *enc, *cat, *comb, *attw;
    cudaGetSymbolAddress((void**)&xW1, g_xW1);
    cudaGetSymbolAddress((void**)&xW2, g_xW2);
    cudaGetSymbolAddress((void**)&enc, g_enc);
    cudaGetSymbolAddress((void**)&cat, g_cat);
    cudaGetSymbolAddress((void**)&comb, g_comb);
    cudaGetSymbolAddress((void**)&attw, g_attw);

    // 1. xW1 = emb[ids] @ Wih^T + bih   [4096 x 2048], K=512 (gather fused)
    gemm_nt_kernel<0><<<dim3(16, 32), 256>>>(emb, Wih, bih, xW1, 4 * Hq, Hq, 4 * Hq, ids);

    // 2. encoder LSTM (persistent, grid-barriered); fills enc and cat[:,512:]
    lstm_enc_kernel<<<NBLK_LSTM, 256>>>(Whh, bhh);

    // 3. xW2 = enc @ Wp_ih^T + bp_ih   [4096 x 80], K=512
    gemm_nt_kernel<0><<<dim3(1, 32), 256>>>(enc, Wpih, bpih, xW2, 4 * Pq, Hq, 4 * Pq, nullptr);

    // 4. positional LSTM + mw/sigma heads + mu scan
    lstm_pw_kernel<<<1, 320>>>(Wphh, bphh, Wmu, bmu, Wsig, bsig, padl);

    // 5. attention weight rows
    attn_w_kernel<<<dim3(Tq, Bq), 256>>>();

    // 6. ctx = w @ enc (batched NN) -> cat[:, :512]
    gemm_nn_kernel<<<dim3(Hq / 128, Tq / 128, Bq), 256>>>(
        attw, enc, cat, Hq, Tq, Hq, 2 * Hq,
        (size_t)Tq * Tq, (size_t)Tq * Hq, (size_t)Tq * 2 * Hq);

    // 7. combined = tanh(cat @ Wc^T + bc)  [4096 x 512], K=1024
    gemm_nt_kernel<1><<<dim3(4, 32), 256>>>(cat, Wc, bc, comb, Hq, 2 * Hq, Hq, nullptr);

    // 8. logits = combined @ emb^T + dec_bias  [4096 x 32000], K=512
    gemm_nt_kernel<0><<<dim3(Vq / 128, 32), 256>>>(comb, emb, decb, out, Vq, Hq, Vq, nullptr);
}

// round 8
// speedup vs baseline: 1.2425x; 1.2425x over previous
#include <cuda_runtime.h>
#include <cuda_bf16.h>
#include <math.h>
#include <stdint.h>

#define Bq 4
#define Tq 1024
#define Hq 512
#define Pq 20
#define Vq 32000
#define NBLK_LSTM 128

// ---------------- scratch (static device allocations; no cudaMalloc) ----------------
__device__ float g_xW1[Bq * Tq * 4 * Hq];     // 33.5 MB
__device__ float g_xW2[Bq * Tq * 4 * Pq];     // 1.3 MB
__device__ float g_enc[Bq * Tq * Hq];         // 8.4 MB
__device__ float g_cat[Bq * Tq * 2 * Hq];     // 16.8 MB  [ctx | enc]
__device__ float g_comb[Bq * Tq * Hq];        // 8.4 MB
__device__ float g_attw[(size_t)Bq * Tq * Tq];// 16.8 MB
__device__ float g_mu[Bq * Tq];
__device__ float g_sigma[Bq * Tq];
__device__ unsigned g_bar_cnt = 0;
__device__ unsigned g_bar_gen = 0;
// bf16 hi/lo splits for tensor-core decoder
__device__ __nv_bfloat16 g_emb_hi[(size_t)Vq * Hq];
__device__ __nv_bfloat16 g_emb_lo[(size_t)Vq * Hq];
__device__ __nv_bfloat16 g_comb_hi[Bq * Tq * Hq];
__device__ __nv_bfloat16 g_comb_lo[Bq * Tq * Hq];

__device__ __forceinline__ float sigmoidf_(float x) { return 1.0f / (1.0f + expf(-x)); }

// ---------------- warp-level bf16 MMA helpers (sm_80+ baseline) ----------------
#define LDSM_X4(r, addr) \
    asm volatile("ldmatrix.sync.aligned.m8n8.x4.shared.b16 {%0,%1,%2,%3}, [%4];" \
        : "=r"((r)[0]), "=r"((r)[1]), "=r"((r)[2]), "=r"((r)[3]) : "r"(addr))

__device__ __forceinline__ void mma_bf16(float* d, const uint32_t* a,
                                         uint32_t b0, uint32_t b1) {
    asm volatile(
        "mma.sync.aligned.m16n8k16.row.col.f32.bf16.bf16.f32 "
        "{%0,%1,%2,%3}, {%4,%5,%6,%7}, {%8,%9}, {%0,%1,%2,%3};"
        : "+f"(d[0]), "+f"(d[1]), "+f"(d[2]), "+f"(d[3])
        : "r"(a[0]), "r"(a[1]), "r"(a[2]), "r"(a[3]), "r"(b0), "r"(b1));
}

// =====================================================================
// Generic NT GEMM: C[M,N] = act(A[M,K] * B[N,K]^T + bias[N])  (fp32 SIMT)
// =====================================================================
template <int ACT>
__global__ void __launch_bounds__(256, 2) gemm_nt_kernel(
    const float* __restrict__ A, const float* __restrict__ Bm,
    const float* __restrict__ bias, float* __restrict__ C,
    int N, int K, int ldc, const int* __restrict__ a_rows)
{
    __shared__ float As[16][128];
    __shared__ float Bs[16][128];
    const int bm = blockIdx.y << 7;
    const int bn = blockIdx.x << 7;
    const int tid = threadIdx.x;
    const int lr = tid >> 2;
    const int lc = (tid & 3) << 2;

    const int am0 = bm + lr, am1 = bm + lr + 64;
    const float* Ar0 = A + (size_t)(a_rows ? a_rows[am0] : am0) * K + lc;
    const float* Ar1 = A + (size_t)(a_rows ? a_rows[am1] : am1) * K + lc;
    const int bn0 = bn + lr, bn1 = bn + lr + 64;
    const float* Br0 = (bn0 < N) ? (Bm + (size_t)bn0 * K + lc) : 0;
    const float* Br1 = (bn1 < N) ? (Bm + (size_t)bn1 * K + lc) : 0;

    const int ty = tid >> 4, tx = tid & 15;
    float acc[8][8];
#pragma unroll
    for (int i = 0; i < 8; i++)
#pragma unroll
        for (int j = 0; j < 8; j++) acc[i][j] = 0.f;

    for (int k0 = 0; k0 < K; k0 += 16) {
        float4 a0 = *(const float4*)(Ar0 + k0);
        float4 a1 = *(const float4*)(Ar1 + k0);
        float4 b0 = Br0 ? *(const float4*)(Br0 + k0) : make_float4(0.f, 0.f, 0.f, 0.f);
        float4 b1 = Br1 ? *(const float4*)(Br1 + k0) : make_float4(0.f, 0.f, 0.f, 0.f);
        __syncthreads();
        As[lc + 0][lr] = a0.x; As[lc + 1][lr] = a0.y; As[lc + 2][lr] = a0.z; As[lc + 3][lr] = a0.w;
        As[lc + 0][lr + 64] = a1.x; As[lc + 1][lr + 64] = a1.y; As[lc + 2][lr + 64] = a1.z; As[lc + 3][lr + 64] = a1.w;
        Bs[lc + 0][lr] = b0.x; Bs[lc + 1][lr] = b0.y; Bs[lc + 2][lr] = b0.z; Bs[lc + 3][lr] = b0.w;
        Bs[lc + 0][lr + 64] = b1.x; Bs[lc + 1][lr + 64] = b1.y; Bs[lc + 2][lr + 64] = b1.z; Bs[lc + 3][lr + 64] = b1.w;
        __syncthreads();
#pragma unroll
        for (int kk = 0; kk < 16; ++kk) {
            float av[8], bv[8];
            *(float4*)(av)     = *(const float4*)&As[kk][ty << 3];
            *(float4*)(av + 4) = *(const float4*)&As[kk][(ty << 3) + 4];
            *(float4*)(bv)     = *(const float4*)&Bs[kk][tx << 3];
            *(float4*)(bv + 4) = *(const float4*)&Bs[kk][(tx << 3) + 4];
#pragma unroll
            for (int i = 0; i < 8; i++)
#pragma unroll
                for (int j = 0; j < 8; j++) acc[i][j] = fmaf(av[i], bv[j], acc[i][j]);
        }
    }
#pragma unroll
    for (int i = 0; i < 8; i++) {
        const int row = bm + (ty << 3) + i;
        float* Cr = C + (size_t)row * ldc;
#pragma unroll
        for (int j = 0; j < 8; j++) {
            const int col = bn + (tx << 3) + j;
            if (col < N) {
                float v = acc[i][j] + (bias ? bias[col] : 0.f);
                if (ACT == 1) v = tanhf(v);
                Cr[col] = v;
            }
        }
    }
}

// =====================================================================
// Batched NN GEMM: C[M,N] = A[M,K] * B[K,N]; batch via blockIdx.z.
// =====================================================================
__global__ void __launch_bounds__(256, 2) gemm_nn_kernel(
    const float* __restrict__ A, const float* __restrict__ Bm,
    float* __restrict__ C, int N, int K, int ldb, int ldc,
    size_t sA, size_t sB, size_t sC)
{
    A += (size_t)blockIdx.z * sA;
    Bm += (size_t)blockIdx.z * sB;
    C += (size_t)blockIdx.z * sC;
    __shared__ float As[16][128];
    __shared__ float Bs[16][128];
    const int bm = blockIdx.y << 7, bn = blockIdx.x << 7;
    const int tid = threadIdx.x;
    const int lr = tid >> 2, lc = (tid & 3) << 2;
    const float* Ar0 = A + (size_t)(bm + lr) * K + lc;
    const float* Ar1 = A + (size_t)(bm + lr + 64) * K + lc;
    const int kb = tid >> 5;
    const int nb = (tid & 31) << 2;
    const float* Bp0 = Bm + (size_t)kb * ldb + bn + nb;
    const float* Bp1 = Bm + (size_t)(kb + 8) * ldb + bn + nb;

    const int ty = tid >> 4, tx = tid & 15;
    float acc[8][8];
#pragma unroll
    for (int i = 0; i < 8; i++)
#pragma unroll
        for (int j = 0; j < 8; j++) acc[i][j] = 0.f;

    for (int k0 = 0; k0 < K; k0 += 16) {
        float4 a0 = *(const float4*)(Ar0 + k0);
        float4 a1 = *(const float4*)(Ar1 + k0);
        float4 b0 = *(const float4*)(Bp0 + (size_t)k0 * ldb);
        float4 b1 = *(const float4*)(Bp1 + (size_t)k0 * ldb);
        __syncthreads();
        As[lc + 0][lr] = a0.x; As[lc + 1][lr] = a0.y; As[lc + 2][lr] = a0.z; As[lc + 3][lr] = a0.w;
        As[lc + 0][lr + 64] = a1.x; As[lc + 1][lr + 64] = a1.y; As[lc + 2][lr + 64] = a1.z; As[lc + 3][lr + 64] = a1.w;
        *(float4*)&Bs[kb][nb] = b0;
        *(float4*)&Bs[kb + 8][nb] = b1;
        __syncthreads();
#pragma unroll
        for (int kk = 0; kk < 16; ++kk) {
            float av[8], bv[8];
            *(float4*)(av)     = *(const float4*)&As[kk][ty << 3];
            *(float4*)(av + 4) = *(const float4*)&As[kk][(ty << 3) + 4];
            *(float4*)(bv)     = *(const float4*)&Bs[kk][tx << 3];
            *(float4*)(bv + 4) = *(const float4*)&Bs[kk][(tx << 3) + 4];
#pragma unroll
            for (int i = 0; i < 8; i++)
#pragma unroll
                for (int j = 0; j < 8; j++) acc[i][j] = fmaf(av[i], bv[j], acc[i][j]);
        }
    }
#pragma unroll
    for (int i = 0; i < 8; i++) {
        const int row = bm + (ty << 3) + i;
        float* Cr = C + (size_t)row * ldc + bn + (tx << 3);
#pragma unroll
        for (int j = 0; j < 8; j++) Cr[j] = acc[i][j];
    }
}

// =====================================================================
// Encoder LSTM: persistent kernel, 128 blocks x 256 threads (unchanged).
// =====================================================================
__global__ void __launch_bounds__(256) lstm_enc_kernel(
    const float* __restrict__ Whh, const float* __restrict__ bhh)
{
    const int g = blockIdx.x;
    const int tid = threadIdx.x;
    __shared__ float Wsh[16][512];
    __shared__ float hsh[4][512];
    __shared__ float gsum[16][4];
    const int j0 = g << 2;

    for (int i = tid; i < 16 * 512; i += 256) {
        const int r = i >> 9, c = i & 511;
        Wsh[r][c] = Whh[(size_t)((r >> 2) * 512 + j0 + (r & 3)) * 512 + c];
    }
    const int bb = tid >> 2, jj = tid & 3;
    float bh[4] = {0.f, 0.f, 0.f, 0.f};
    if (tid < 16) {
#pragma unroll
        for (int q = 0; q < 4; q++) bh[q] = bhh[q * 512 + j0 + jj];
    }
    float cst = 0.f;
    unsigned gen = *(volatile unsigned*)&g_bar_gen;
    const int w = tid >> 5, lane = tid & 31;
    const int r0 = w << 1, r1 = r0 + 1;
    __syncthreads();

    for (int t = 0; t < Tq; ++t) {
        if (t == 0) {
            for (int i = tid; i < 2048; i += 256) ((float*)hsh)[i] = 0.f;
        } else {
            for (int i = tid; i < 2048; i += 256) {
                const int b = i >> 9, c = i & 511;
                ((float*)hsh)[i] = __ldcg(&g_enc[((size_t)b * Tq + (t - 1)) * Hq + c]);
            }
        }
        __syncthreads();

        float a0[4] = {0.f, 0.f, 0.f, 0.f}, a1[4] = {0.f, 0.f, 0.f, 0.f};
#pragma unroll 4
        for (int c = lane; c < 512; c += 32) {
            const float w0 = Wsh[r0][c], w1 = Wsh[r1][c];
#pragma unroll
            for (int b = 0; b < 4; b++) {
                const float hv = hsh[b][c];
                a0[b] = fmaf(w0, hv, a0[b]);
                a1[b] = fmaf(w1, hv, a1[b]);
            }
        }
#pragma unroll
        for (int off = 16; off; off >>= 1) {
#pragma unroll
            for (int b = 0; b < 4; b++) {
                a0[b] += __shfl_xor_sync(0xffffffffu, a0[b], off);
                a1[b] += __shfl_xor_sync(0xffffffffu, a1[b], off);
            }
        }
        if (lane == 0) {
#pragma unroll
            for (int b = 0; b < 4; b++) { gsum[r0][b] = a0[b]; gsum[r1][b] = a1[b]; }
        }
        __syncthreads();

        if (tid < 16) {
            float pre[4];
#pragma unroll
            for (int q = 0; q < 4; q++)
                pre[q] = __ldcg(&g_xW1[((size_t)bb * Tq + t) * 2048 + q * 512 + j0 + jj])
                         + gsum[(q << 2) + jj][bb] + bh[q];
            const float ig = sigmoidf_(pre[0]);
            const float fg = sigmoidf_(pre[1]);
            const float gg = tanhf(pre[2]);
            const float og = sigmoidf_(pre[3]);
            cst = fg * cst + ig * gg;
            const float h = og * tanhf(cst);
            g_enc[((size_t)bb * Tq + t) * Hq + j0 + jj] = h;
            g_cat[((size_t)bb * Tq + t) * 1024 + 512 + j0 + jj] = h;
            __threadfence();
        }
        __syncthreads();
        if (tid == 0) {
            const unsigned target = gen + 1;
            const unsigned arrived = atomicAdd(&g_bar_cnt, 1u);
            if (arrived == NBLK_LSTM - 1) {
                g_bar_cnt = 0u;
                __threadfence();
                *(volatile unsigned*)&g_bar_gen = target;
            } else {
                while (*(volatile unsigned*)&g_bar_gen != target) {}
            }
            __threadfence();
        }
        gen++;
        __syncthreads();
    }
}

// =====================================================================
// Positional LSTM (P=20): one warp per batch, register weights,
// syncwarp-only, shuffle-reduced heads + mu scan on lane 0.
// =====================================================================
__global__ void __launch_bounds__(32) lstm_pw_kernel(
    const float* __restrict__ Wp_hh, const float* __restrict__ bp_hh,
    const float* __restrict__ Wmu, const float* __restrict__ bmu,
    const float* __restrict__ Wsig, const float* __restrict__ bsig,
    const int* __restrict__ pad_lengths)
{
    const int b = blockIdx.x;
    const int l = threadIdx.x;
    __shared__ float hp[20];
    __shared__ float gs[80];
    const int r0 = l, r1 = 32 + l, r2 = 64 + l;
    float w0[20], w1[20], w2[20];
    const float bb0 = bp_hh[r0];
    const float bb1 = bp_hh[r1];
    const float bb2 = (l < 16) ? bp_hh[r2] : 0.f;
#pragma unroll
    for (int c = 0; c < 20; c++) {
        w0[c] = Wp_hh[r0 * 20 + c];
        w1[c] = Wp_hh[r1 * 20 + c];
        w2[c] = (l < 16) ? Wp_hh[r2 * 20 + c] : 0.f;
    }
    float wm0 = 0.f, wm1 = 0.f, wm2 = 0.f, ws = 0.f;
    if (l < 20) { wm0 = Wmu[l]; wm1 = Wmu[20 + l]; wm2 = Wmu[40 + l]; ws = Wsig[l]; }
    const float bm0 = bmu[0], bm1 = bmu[1], bm2 = bmu[2], bs0 = bsig[0];
    const float invL = 1.0f / (float)pad_lengths[b];
    float cst = 0.f, muprev = 0.f;
    if (l < 20) hp[l] = 0.f;
    __syncwarp();

    const float* xbase = g_xW2 + (size_t)b * Tq * 80;
    float x0 = __ldcg(xbase + r0);
    float x1 = __ldcg(xbase + r1);
    float x2 = (l < 16) ? __ldcg(xbase + r2) : 0.f;
    for (int t = 0; t < Tq; ++t) {
        float s0 = x0 + bb0, s1 = x1 + bb1, s2 = x2 + bb2;
#pragma unroll
        for (int c = 0; c < 20; c++) {
            const float hv = hp[c];
            s0 = fmaf(w0[c], hv, s0);
            s1 = fmaf(w1[c], hv, s1);
            s2 = fmaf(w2[c], hv, s2);
        }
        gs[r0] = s0; gs[r1] = s1;
        if (l < 16) gs[r2] = s2;
        if (t + 1 < Tq) {
            const float* xb = xbase + (size_t)(t + 1) * 80;
            x0 = __ldcg(xb + r0); x1 = __ldcg(xb + r1);
            x2 = (l < 16) ? __ldcg(xb + r2) : 0.f;
        }
        __syncwarp();
        float h = 0.f;
        if (l < 20) {
            const float ig = sigmoidf_(gs[l]);
            const float fg = sigmoidf_(gs[20 + l]);
            const float gg = tanhf(gs[40 + l]);
            const float og = sigmoidf_(gs[60 + l]);
            cst = fg * cst + ig * gg;
            h = og * tanhf(cst);
            hp[l] = h;
        }
        float p0 = wm0 * h, p1 = wm1 * h, p2 = wm2 * h, ps = ws * h;
#pragma unroll
        for (int off = 16; off; off >>= 1) {
            p0 += __shfl_xor_sync(0xffffffffu, p0, off);
            p1 += __shfl_xor_sync(0xffffffffu, p1, off);
            p2 += __shfl_xor_sync(0xffffffffu, p2, off);
            ps += __shfl_xor_sync(0xffffffffu, ps, off);
        }
        if (l == 0) {
            const float m0 = fmaxf(p0 + bm0, 0.f);
            const float m1 = fmaxf(p1 + bm1, 0.f);
            const float m2 = fmaxf(p2 + bm2, 0.f);
            const float sg = sigmoidf_(ps + bs0);
            muprev = m0 * muprev + m1 * invL + m2 * ((float)(t + 1) * invL);
            g_mu[b * Tq + t] = muprev;
            g_sigma[b * Tq + t] = sg;
        }
        __syncwarp();
    }
}

// =====================================================================
// Attention weights (unchanged)
// =====================================================================
__global__ void __launch_bounds__(256) attn_w_kernel()
{
    const int j = blockIdx.x;
    const int b = blockIdx.y;
    const int tid = threadIdx.x;
    __shared__ float row[Tq];
    __shared__ float warpsum[8];
    __shared__ float invtot;
    const float m = g_mu[b * Tq + j];
    const float s = g_sigma[b * Tq + j];
    const float inv2s = 1.0f / (2.0f * s * s + 0.001f);
    const float jp1 = (float)(j + 1);
    float lsum = 0.f;
    for (int t = tid; t < Tq; t += 256) {
        float v = 0.f;
        if (t <= j) {
            const float d = (float)t / jp1 - m;
            v = expf(-(d * d) * inv2s);
        }
        row[t] = v;
        lsum += v;
    }
#pragma unroll
    for (int off = 16; off; off >>= 1) lsum += __shfl_xor_sync(0xffffffffu, lsum, off);
    if ((tid & 31) == 0) warpsum[tid >> 5] = lsum;
    __syncthreads();
    if (tid == 0) {
        float tot = 0.f;
#pragma unroll
        for (int i = 0; i < 8; i++) tot += warpsum[i];
        invtot = 1.0f / fmaxf(tot, 1e-12f);
    }
    __syncthreads();
    const float inv = invtot;
    float* out = &g_attw[((size_t)b * Tq + j) * Tq];
    for (int t = tid; t < Tq; t += 256) out[t] = row[t] * inv;
}

// =====================================================================
// fp32 -> bf16 hi/lo split (for tensor-core decoder)
// =====================================================================
__global__ void __launch_bounds__(256) cvt_split_kernel(
    const float* __restrict__ src, __nv_bfloat16* __restrict__ hi,
    __nv_bfloat16* __restrict__ lo, int n4)
{
    const int i = blockIdx.x * 256 + threadIdx.x;
    if (i >= n4) return;
    const float4 v = ((const float4*)src)[i];
    const __nv_bfloat16 h0 = __float2bfloat16(v.x);
    const __nv_bfloat16 h1 = __float2bfloat16(v.y);
    const __nv_bfloat16 h2 = __float2bfloat16(v.z);
    const __nv_bfloat16 h3 = __float2bfloat16(v.w);
    const __nv_bfloat16 l0 = __float2bfloat16(v.x - __bfloat162float(h0));
    const __nv_bfloat16 l1 = __float2bfloat16(v.y - __bfloat162float(h1));
    const __nv_bfloat16 l2 = __float2bfloat16(v.z - __bfloat162float(h2));
    const __nv_bfloat16 l3 = __float2bfloat16(v.w - __bfloat162float(h3));
    __nv_bfloat162* hp = (__nv_bfloat162*)hi;
    __nv_bfloat162* lp = (__nv_bfloat162*)lo;
    hp[2 * i]     = __nv_bfloat162(h0, h1);
    hp[2 * i + 1] = __nv_bfloat162(h2, h3);
    lp[2 * i]     = __nv_bfloat162(l0, l1);
    lp[2 * i + 1] = __nv_bfloat162(l2, l3);
}

// =====================================================================
// Decoder GEMM via warp-level bf16 mma.sync (3-split, fp32 accum):
// C[4096,32000] = A[4096,512] * B[32000,512]^T + bias.
// Block tile 128x128, 256 threads (8 warps, 4x2), warp tile 32x64.
// K chunks of 32; single 40KB smem stage + register prefetch.
// smem rows padded to 80B so ldmatrix is bank-conflict-free.
// =====================================================================
#define DKC 32
#define DCH (Hq / DKC)            // 16 chunks
#define TPAD 40                   // halfwords per smem row
#define TILE_HW (128 * TPAD)      // 5120 halfwords = 10240 B per tile
__global__ void __launch_bounds__(256) dec_mma_kernel(
    const __nv_bfloat16* __restrict__ Ahi, const __nv_bfloat16* __restrict__ Alo,
    const __nv_bfloat16* __restrict__ Bhi, const __nv_bfloat16* __restrict__ Blo,
    const float* __restrict__ bias, float* __restrict__ C)
{
    __shared__ __align__(16) __nv_bfloat16 sbuf[4 * TILE_HW];   // 40 KB
    const int tid = threadIdx.x;
    const int lane = tid & 31, wid = tid >> 5;
    const size_t am0 = (size_t)blockIdx.y * 128;
    const size_t bn0 = (size_t)blockIdx.x * 128;

    // ---- per-thread global->smem copy plan (8 x uint4 per chunk) ----
    const __nv_bfloat16* tb[4] = {Ahi + am0 * Hq, Alo + am0 * Hq,
                                  Bhi + bn0 * Hq, Blo + bn0 * Hq};
    const __nv_bfloat16* srcp[8];
    uint32_t dsto[8];
#pragma unroll
    for (int t = 0; t < 8; ++t) {
        const int tile = t >> 1;                    // compile-time
        const int rem = tid + (t & 1) * 256;        // 0..511
        const int row = rem >> 2, c4 = rem & 3;
        srcp[t] = tb[tile] + (size_t)row * Hq + c4 * 8;
        dsto[t] = (uint32_t)(tile * (TILE_HW * 2) + row * (TPAD * 2) + c4 * 16); // bytes
    }
    char* sbase_c = (char*)sbuf;

    // preload chunk 0
    uint4 pf[8];
#pragma unroll
    for (int t = 0; t < 8; ++t) pf[t] = *(const uint4*)(srcp[t]);
#pragma unroll
    for (int t = 0; t < 8; ++t) *(uint4*)(sbase_c + dsto[t]) = pf[t];
    __syncthreads();

    // ---- mma setup ----
    const int wm = (wid & 3) * 32;      // warp row offset (0..96)
    const int wn = (wid >> 2) * 64;     // warp col offset (0/64)
    const uint32_t sb = (uint32_t)__cvta_generic_to_shared(sbuf);
    const int lrow = (lane & 7) + ((lane >> 3) & 1) * 8;  // ldmatrix row-within-16
    const int lkb  = (lane >> 4) * 16;                    // ldmatrix byte half

    float d[2][8][4];
#pragma unroll
    for (int mi = 0; mi < 2; mi++)
#pragma unroll
        for (int nt = 0; nt < 8; nt++)
#pragma unroll
            for (int e = 0; e < 4; e++) d[mi][nt][e] = 0.f;

    for (int c = 0; c < DCH; ++c) {
        if (c + 1 < DCH) {
            const int ko = (c + 1) * DKC;
#pragma unroll
            for (int t = 0; t < 8; ++t) pf[t] = *(const uint4*)(srcp[t] + ko);
        }
#pragma unroll
        for (int s = 0; s < 2; ++s) {
            const uint32_t kbyte = s * 32 + lkb;
            uint32_t ah[2][4], al[2][4];
#pragma unroll
            for (int mi = 0; mi < 2; mi++) {
                const uint32_t ra = sb + (wm + mi * 16 + lrow) * (TPAD * 2) + kbyte;
                LDSM_X4(ah[mi], ra);
                LDSM_X4(al[mi], ra + TILE_HW * 2);
            }
#pragma unroll
            for (int ng = 0; ng < 4; ng++) {
                const uint32_t rb = sb + 2 * TILE_HW * 2
                                    + (wn + ng * 16 + lrow) * (TPAD * 2) + kbyte;
                uint32_t bh[4], bl[4];
                LDSM_X4(bh, rb);
                LDSM_X4(bl, rb + TILE_HW * 2);
#pragma unroll
                for (int mi = 0; mi < 2; mi++) {
                    mma_bf16(d[mi][2 * ng],     ah[mi], bh[0], bh[2]);
                    mma_bf16(d[mi][2 * ng + 1], ah[mi], bh[1], bh[3]);
                    mma_bf16(d[mi][2 * ng],     ah[mi], bl[0], bl[2]);
                    mma_bf16(d[mi][2 * ng + 1], ah[mi], bl[1], bl[3]);
                    mma_bf16(d[mi][2 * ng],     al[mi], bh[0], bh[2]);
                    mma_bf16(d[mi][2 * ng + 1], al[mi], bh[1], bh[3]);
                }
            }
        }
        __syncthreads();
        if (c + 1 < DCH) {
#pragma unroll
            for (int t = 0; t < 8; ++t) *(uint4*)(sbase_c + dsto[t]) = pf[t];
        }
        __syncthreads();
    }

    // ---- epilogue: C frag (row = lane/4 (+8), col = (lane%4)*2 (+1)) ----
#pragma unroll
    for (int mi = 0; mi < 2; mi++) {
        const size_t row0 = am0 + wm + mi * 16 + (lane >> 2);
#pragma unroll
        for (int nt = 0; nt < 8; nt++) {
            const size_t col = bn0 + wn + nt * 8 + (lane & 3) * 2;
            const float b0 = __ldg(&bias[col]);
            const float b1 = __ldg(&bias[col + 1]);
            float2 v0 = make_float2(d[mi][nt][0] + b0, d[mi][nt][1] + b1);
            float2 v1 = make_float2(d[mi][nt][2] + b0, d[mi][nt][3] + b1);
            *(float2*)(C + row0 * Vq + col) = v0;
            *(float2*)(C + (row0 + 8) * Vq + col) = v1;
        }
    }
}

// =====================================================================
extern "C" void kernel_launch(void* const* d_in, const int* in_sizes, int n_in,
                              void* d_out, int out_size)
{
    (void)in_sizes; (void)n_in; (void)out_size;
    const int*   ids  = (const int*)d_in[0];
    const int*   padl = (const int*)d_in[1];
    const float* emb  = (const float*)d_in[2];
    const float* decb = (const float*)d_in[3];
    const float* Wih  = (const float*)d_in[4];
    const float* Whh  = (const float*)d_in[5];
    const float* bih  = (const float*)d_in[6];
    const float* bhh  = (const float*)d_in[7];
    const float* Wpih = (const float*)d_in[8];
    const float* Wphh = (const float*)d_in[9];
    const float* bpih = (const float*)d_in[10];
    const float* bphh = (const float*)d_in[11];
    const float* Wmu  = (const float*)d_in[12];
    const float* bmu  = (const float*)d_in[13];
    const float* Wsig = (const float*)d_in[14];
    const float* bsig = (const float*)d_in[15];
    const float* Wc   = (const float*)d_in[16];
    const float* bc   = (const float*)d_in[17];
    float* out = (float*)d_out;

    float *xW1, *xW2, *enc, *cat, *comb, *attw;
    __nv_bfloat16 *ehi, *elo, *chi, *clo;
    cudaGetSymbolAddress((void**)&xW1, g_xW1);
    cudaGetSymbolAddress((void**)&xW2, g_xW2);
    cudaGetSymbolAddress((void**)&enc, g_enc);
    cudaGetSymbolAddress((void**)&cat, g_cat);
    cudaGetSymbolAddress((void**)&comb, g_comb);
    cudaGetSymbolAddress((void**)&attw, g_attw);
    cudaGetSymbolAddress((void**)&ehi, g_emb_hi);
    cudaGetSymbolAddress((void**)&elo, g_emb_lo);
    cudaGetSymbolAddress((void**)&chi, g_comb_hi);
    cudaGetSymbolAddress((void**)&clo, g_comb_lo);

    // 0. emb -> bf16 hi/lo split (for decoder)
    {
        const int n4 = Vq * Hq / 4;
        cvt_split_kernel<<<(n4 + 255) / 256, 256>>>(emb, ehi, elo, n4);
    }

    // 1. xW1 = emb[ids] @ Wih^T + bih   [4096 x 2048], K=512 (gather fused)
    gemm_nt_kernel<0><<<dim3(16, 32), 256>>>(emb, Wih, bih, xW1, 4 * Hq, Hq, 4 * Hq, ids);

    // 2. encoder LSTM (persistent, grid-barriered); fills enc and cat[:,512:]
    lstm_enc_kernel<<<NBLK_LSTM, 256>>>(Whh, bhh);

    // 3. xW2 = enc @ Wp_ih^T + bp_ih   [4096 x 80], K=512
    gemm_nt_kernel<0><<<dim3(1, 32), 256>>>(enc, Wpih, bpih, xW2, 4 * Pq, Hq, 4 * Pq, nullptr);

    // 4. positional LSTM + heads + mu scan (one warp per batch)
    lstm_pw_kernel<<<Bq, 32>>>(Wphh, bphh, Wmu, bmu, Wsig, bsig, padl);

    // 5. attention weight rows
    attn_w_kernel<<<dim3(Tq, Bq), 256>>>();

    // 6. ctx = w @ enc (batched NN) -> cat[:, :512]
    gemm_nn_kernel<<<dim3(Hq / 128, Tq / 128, Bq), 256>>>(
        attw, enc, cat, Hq, Tq, Hq, 2 * Hq,
        (size_t)Tq * Tq, (size_t)Tq * Hq, (size_t)Tq * 2 * Hq);

    // 7. combined = tanh(cat @ Wc^T + bc)  [4096 x 512], K=1024
    gemm_nt_kernel<1><<<dim3(4, 32), 256>>>(cat, Wc, bc, comb, Hq, 2 * Hq, Hq, nullptr);

    // 7b. comb -> bf16 hi/lo
    {
        const int n4 = Bq * Tq * Hq / 4;
        cvt_split_kernel<<<(n4 + 255) / 256, 256>>>(comb, chi, clo, n4);
    }

    // 8. logits = comb @ emb^T + dec_bias via bf16 mma.sync 3-split
    dec_mma_kernel<<<dim3(Vq / 128, 32), 256>>>(chi, clo, ehi, elo, decb, out);
}